// round 1
// baseline (speedup 1.0000x reference)
#include <cuda_runtime.h>
#include <math.h>

// ---------------- problem constants ----------------
#define C_CLS   1000
#define DIMG    2048
#define DATT    312
#define HH      128
#define BB      2048
#define THRESH  0.76604444311897803f   // cos(40 deg)
#define TEMP    32.0f

// ---------------- scratch (device globals; no allocation allowed) -------
__device__ float g_proto_red[C_CLS * DATT];   // [1000,312]
__device__ float g_gn[C_CLS * HH];            // [1000,128]
__device__ float g_attn[C_CLS * C_CLS];       // [1000,1000]
__device__ float g_M[C_CLS * HH];             // [1000,128]
__device__ float g_proto_h[C_CLS * HH];       // [1000,128] (proto_b folded in)
__device__ float g_img_h[BB * HH];            // [2048,128]

// ---------------- generic tiled SGEMM: C = A[MxK] @ B[KxN] (+bias col) (+accum)
// BM=32, BN=64, BK=8, 256 threads, thread tile 2x4
__global__ void sgemm_kernel(const float* __restrict__ A,
                             const float* __restrict__ B,
                             const float* __restrict__ bias,
                             float* __restrict__ C,
                             int M, int N, int K, int accum) {
    __shared__ float As[8][32];
    __shared__ float Bs[8][64];
    const int tid = threadIdx.x;
    const int tx = tid & 15;    // N direction, 4 cols each
    const int ty = tid >> 4;    // M direction, 2 rows each
    const int row0 = blockIdx.y * 32;
    const int col0 = blockIdx.x * 64;

    float acc[2][4] = {{0.f,0.f,0.f,0.f},{0.f,0.f,0.f,0.f}};

    for (int k0 = 0; k0 < K; k0 += 8) {
        {   // load A tile: 32x8 = 256 elems, one per thread
            int r = tid >> 3, c = tid & 7;
            int gr = row0 + r, gc = k0 + c;
            As[c][r] = (gr < M && gc < K) ? A[(size_t)gr * K + gc] : 0.f;
        }
        #pragma unroll
        for (int i = tid; i < 8 * 64; i += 256) {  // load B tile: 8x64
            int r = i >> 6, c = i & 63;
            int gr = k0 + r, gc = col0 + c;
            Bs[r][c] = (gr < K && gc < N) ? B[(size_t)gr * N + gc] : 0.f;
        }
        __syncthreads();
        #pragma unroll
        for (int kk = 0; kk < 8; kk++) {
            float a0 = As[kk][ty * 2 + 0];
            float a1 = As[kk][ty * 2 + 1];
            float b0 = Bs[kk][tx * 4 + 0];
            float b1 = Bs[kk][tx * 4 + 1];
            float b2 = Bs[kk][tx * 4 + 2];
            float b3 = Bs[kk][tx * 4 + 3];
            acc[0][0] = fmaf(a0, b0, acc[0][0]);
            acc[0][1] = fmaf(a0, b1, acc[0][1]);
            acc[0][2] = fmaf(a0, b2, acc[0][2]);
            acc[0][3] = fmaf(a0, b3, acc[0][3]);
            acc[1][0] = fmaf(a1, b0, acc[1][0]);
            acc[1][1] = fmaf(a1, b1, acc[1][1]);
            acc[1][2] = fmaf(a1, b2, acc[1][2]);
            acc[1][3] = fmaf(a1, b3, acc[1][3]);
        }
        __syncthreads();
    }
    #pragma unroll
    for (int i = 0; i < 2; i++) {
        int gr = row0 + ty * 2 + i;
        if (gr >= M) continue;
        #pragma unroll
        for (int j = 0; j < 4; j++) {
            int gc = col0 + tx * 4 + j;
            if (gc >= N) continue;
            float v = acc[i][j];
            if (bias) v += bias[gc];
            if (accum) v += C[(size_t)gr * N + gc];
            C[(size_t)gr * N + gc] = v;
        }
    }
}

// ---------------- gn = normalize_rows(attributes @ att_g) ----------------
// 8 rows per block, 128 threads (one per output column h)
__global__ void gn_kernel(const float* __restrict__ attrs,
                          const float* __restrict__ att_g,
                          float* __restrict__ gn) {
    __shared__ float s_attr[8][DATT];
    __shared__ float s_red[8][4];
    const int c0 = blockIdx.x * 8;
    const int t = threadIdx.x;       // 128
    const int lane = t & 31, warp = t >> 5;

    for (int i = t; i < 8 * DATT; i += 128) {
        int r = i / DATT, k = i - r * DATT;
        s_attr[r][k] = attrs[(size_t)(c0 + r) * DATT + k];
    }
    __syncthreads();

    float acc[8] = {0.f,0.f,0.f,0.f,0.f,0.f,0.f,0.f};
    for (int k = 0; k < DATT; k++) {
        float w = att_g[(size_t)k * HH + t];
        #pragma unroll
        for (int r = 0; r < 8; r++) acc[r] = fmaf(s_attr[r][k], w, acc[r]);
    }
    // per-row L2 norm across 128 threads
    #pragma unroll
    for (int r = 0; r < 8; r++) {
        float sq = acc[r] * acc[r];
        #pragma unroll
        for (int o = 16; o; o >>= 1) sq += __shfl_xor_sync(0xffffffffu, sq, o);
        if (lane == 0) s_red[r][warp] = sq;
    }
    __syncthreads();
    #pragma unroll
    for (int r = 0; r < 8; r++) {
        float tot = s_red[r][0] + s_red[r][1] + s_red[r][2] + s_red[r][3];
        float inv = 1.f / fmaxf(sqrtf(tot), 1e-12f);
        gn[(size_t)(c0 + r) * HH + t] = acc[r] * inv;
    }
}

// ---------------- attn rows: sim = gn@gn^T, mask, softmax(sim*T) ---------
// 4 rows per block, 256 threads (8 warps); warp-per-column dot products
__global__ void attn_kernel(const float* __restrict__ gn,
                            float* __restrict__ attn) {
    __shared__ float s_g[4][HH];
    __shared__ float s_val[4][C_CLS];
    __shared__ float s_red[8];
    const int r0 = blockIdx.x * 4;
    const int t = threadIdx.x, lane = t & 31, warp = t >> 5;

    for (int i = t; i < 4 * HH; i += 256) s_g[i >> 7][i & 127] = gn[(size_t)r0 * HH + i];
    __syncthreads();

    for (int c = warp; c < C_CLS; c += 8) {
        const float* gc = gn + (size_t)c * HH;
        float p0 = 0.f, p1 = 0.f, p2 = 0.f, p3 = 0.f;
        #pragma unroll
        for (int j = 0; j < 4; j++) {
            int k = lane + j * 32;
            float g = gc[k];
            p0 = fmaf(s_g[0][k], g, p0);
            p1 = fmaf(s_g[1][k], g, p1);
            p2 = fmaf(s_g[2][k], g, p2);
            p3 = fmaf(s_g[3][k], g, p3);
        }
        #pragma unroll
        for (int o = 16; o; o >>= 1) {
            p0 += __shfl_xor_sync(0xffffffffu, p0, o);
            p1 += __shfl_xor_sync(0xffffffffu, p1, o);
            p2 += __shfl_xor_sync(0xffffffffu, p2, o);
            p3 += __shfl_xor_sync(0xffffffffu, p3, o);
        }
        if (lane == 0) {
            s_val[0][c] = p0; s_val[1][c] = p1; s_val[2][c] = p2; s_val[3][c] = p3;
        }
    }
    __syncthreads();

    for (int r = 0; r < 4; r++) {
        float locv[4];
        float m = -1e30f;
        #pragma unroll
        for (int i = 0; i < 4; i++) {
            int c = t + i * 256;
            float v = -1e30f;
            if (c < C_CLS) {
                float s = s_val[r][c];
                if (s > THRESH) v = s * TEMP;
            }
            locv[i] = v;
            m = fmaxf(m, v);
        }
        #pragma unroll
        for (int o = 16; o; o >>= 1) m = fmaxf(m, __shfl_xor_sync(0xffffffffu, m, o));
        if (lane == 0) s_red[warp] = m;
        __syncthreads();
        m = s_red[0];
        #pragma unroll
        for (int w = 1; w < 8; w++) m = fmaxf(m, s_red[w]);
        __syncthreads();

        float sum = 0.f;
        #pragma unroll
        for (int i = 0; i < 4; i++) {
            float e = (locv[i] > -1e29f) ? __expf(locv[i] - m) : 0.f;
            locv[i] = e;
            sum += e;
        }
        #pragma unroll
        for (int o = 16; o; o >>= 1) sum += __shfl_xor_sync(0xffffffffu, sum, o);
        if (lane == 0) s_red[warp] = sum;
        __syncthreads();
        float tot = 0.f;
        #pragma unroll
        for (int w = 0; w < 8; w++) tot += s_red[w];
        float inv = 1.f / tot;
        #pragma unroll
        for (int i = 0; i < 4; i++) {
            int c = t + i * 256;
            if (c < C_CLS) attn[(size_t)(r0 + r) * C_CLS + c] = locv[i] * inv;
        }
        __syncthreads();
    }
}

// ---------------- relation MLP: out[b,c] = fc_b + sum_h relu(img_h[b,h]+proto_h[c,h]) * fc_w[h]
// block tile 32 b x 48 c, 256 threads, thread tile 2x3, transposed smem tiles
__global__ void relation_kernel(const float* __restrict__ img_h,
                                const float* __restrict__ proto_h,
                                const float* __restrict__ fc_w,
                                const float* __restrict__ fc_b,
                                float* __restrict__ out) {
    __shared__ float s_a[HH][33];   // [h][b], 32 b
    __shared__ float s_p[HH][49];   // [h][c], 48 c
    __shared__ float s_w[HH];
    const int tid = threadIdx.x;
    const int b0 = blockIdx.y * 32;
    const int c0 = blockIdx.x * 48;

    for (int i = tid; i < 32 * HH; i += 256) {
        int b = i >> 7, h = i & 127;
        s_a[h][b] = img_h[(size_t)(b0 + b) * HH + h];
    }
    for (int i = tid; i < 48 * HH; i += 256) {
        int c = i >> 7, h = i & 127;
        int gc = c0 + c;
        s_p[h][c] = (gc < C_CLS) ? proto_h[(size_t)gc * HH + h] : 0.f;
    }
    if (tid < HH) s_w[tid] = fc_w[tid];
    __syncthreads();

    const int tx = tid & 15;   // c: 3 each
    const int ty = tid >> 4;   // b: 2 each
    float acc[2][3] = {{0.f,0.f,0.f},{0.f,0.f,0.f}};

    #pragma unroll 4
    for (int h = 0; h < HH; h++) {
        float w  = s_w[h];
        float a0 = s_a[h][ty * 2 + 0];
        float a1 = s_a[h][ty * 2 + 1];
        float p0 = s_p[h][tx * 3 + 0];
        float p1 = s_p[h][tx * 3 + 1];
        float p2 = s_p[h][tx * 3 + 2];
        acc[0][0] = fmaf(fmaxf(a0 + p0, 0.f), w, acc[0][0]);
        acc[0][1] = fmaf(fmaxf(a0 + p1, 0.f), w, acc[0][1]);
        acc[0][2] = fmaf(fmaxf(a0 + p2, 0.f), w, acc[0][2]);
        acc[1][0] = fmaf(fmaxf(a1 + p0, 0.f), w, acc[1][0]);
        acc[1][1] = fmaf(fmaxf(a1 + p1, 0.f), w, acc[1][1]);
        acc[1][2] = fmaf(fmaxf(a1 + p2, 0.f), w, acc[1][2]);
    }

    const float bias = fc_b[0];
    #pragma unroll
    for (int i = 0; i < 2; i++) {
        int b = b0 + ty * 2 + i;
        #pragma unroll
        for (int j = 0; j < 3; j++) {
            int c = c0 + tx * 3 + j;
            if (c < C_CLS) out[(size_t)b * C_CLS + c] = acc[i][j] + bias;
        }
    }
}

// ---------------- host launch ----------------
static inline dim3 sgemm_grid(int M, int N) {
    return dim3((N + 63) / 64, (M + 31) / 32);
}

extern "C" void kernel_launch(void* const* d_in, const int* in_sizes, int n_in,
                              void* d_out, int out_size) {
    const float* image_feats = (const float*)d_in[0];  // [2048,2048]
    const float* img_proto   = (const float*)d_in[1];  // [1000,2048]
    const float* attributes  = (const float*)d_in[2];  // [1000,312]
    // d_in[3] = unused
    const float* att_g   = (const float*)d_in[4];      // [312,128]
    const float* slim_w  = (const float*)d_in[5];      // [2048,312]
    const float* slim_b  = (const float*)d_in[6];      // [312]
    const float* img_w   = (const float*)d_in[7];      // [2048,128]
    const float* proto_w = (const float*)d_in[8];      // [624,128]
    const float* proto_b = (const float*)d_in[9];      // [1,128]
    const float* fc_w    = (const float*)d_in[10];     // [128,1]
    const float* fc_b    = (const float*)d_in[11];     // [1]
    float* out = (float*)d_out;

    float *proto_red, *gnp, *attnp, *Mp, *proto_hp, *img_hp;
    cudaGetSymbolAddress((void**)&proto_red, g_proto_red);
    cudaGetSymbolAddress((void**)&gnp,       g_gn);
    cudaGetSymbolAddress((void**)&attnp,     g_attn);
    cudaGetSymbolAddress((void**)&Mp,        g_M);
    cudaGetSymbolAddress((void**)&proto_hp,  g_proto_h);
    cudaGetSymbolAddress((void**)&img_hp,    g_img_h);

    // proto_red = img_proto @ slim_w + slim_b          [1000,312]
    sgemm_kernel<<<sgemm_grid(C_CLS, DATT), 256>>>(
        img_proto, slim_w, slim_b, proto_red, C_CLS, DATT, DIMG, 0);

    // gn = normalize_rows(attributes @ att_g)          [1000,128]
    gn_kernel<<<C_CLS / 8, 128>>>(attributes, att_g, gnp);

    // attn = softmax(mask(gn@gn^T) * T)                [1000,1000]
    attn_kernel<<<C_CLS / 4, 256>>>(gnp, attnp);

    // M = attributes @ proto_w[0:312] + proto_red @ proto_w[312:624]   [1000,128]
    sgemm_kernel<<<sgemm_grid(C_CLS, HH), 256>>>(
        attributes, proto_w, nullptr, Mp, C_CLS, HH, DATT, 0);
    sgemm_kernel<<<sgemm_grid(C_CLS, HH), 256>>>(
        proto_red, proto_w + (size_t)DATT * HH, nullptr, Mp, C_CLS, HH, DATT, 1);

    // proto_h = attn @ M + proto_b                     [1000,128]
    sgemm_kernel<<<sgemm_grid(C_CLS, HH), 256>>>(
        attnp, Mp, proto_b, proto_hp, C_CLS, HH, C_CLS, 0);

    // img_h = image_feats @ img_w                      [2048,128]
    sgemm_kernel<<<sgemm_grid(BB, HH), 256>>>(
        image_feats, img_w, nullptr, img_hp, BB, HH, DIMG, 0);

    // out[b,c] = fc_b + relu(img_h[b]+proto_h[c]) . fc_w
    dim3 rgrid((C_CLS + 47) / 48, BB / 32);
    relation_kernel<<<rgrid, 256>>>(img_hp, proto_hp, fc_w, fc_b, out);
}

// round 2
// speedup vs baseline: 2.4075x; 2.4075x over previous
#include <cuda_runtime.h>
#include <math.h>

// ---------------- problem constants ----------------
#define C_CLS   1000
#define DIMG    2048
#define DATT    312
#define HH      128
#define BB      2048
#define THRESH  0.76604444311897803f   // cos(40 deg)
#define TEMP    32.0f

typedef unsigned long long ull;

// ---------------- scratch (device globals; no allocation allowed) -------
__device__ float g_proto_red[C_CLS * DATT];        // [1000,312]
__device__ float g_gn[C_CLS * HH];                 // [1000,128]
__device__ float g_attn[C_CLS * C_CLS];            // [1000,1000]
__device__ float g_M[C_CLS * HH];                  // [1000,128] (proto_b folded)
__device__ float g_proto_h[C_CLS * HH];            // [1000,128]
__device__ float g_img_h[BB * HH];                 // [2048,128]
__device__ float g_scratch[4 * C_CLS * DATT];      // split-K partials (5MB)

// ---------------- packed f32x2 helpers ----------------
__device__ __forceinline__ ull pk2(float x, float y) {
    ull r;
    asm("mov.b64 %0, {%1, %2};" : "=l"(r) : "r"(__float_as_uint(x)), "r"(__float_as_uint(y)));
    return r;
}
__device__ __forceinline__ ull fma2(ull a, ull b, ull c) {
    ull d;
    asm("fma.rn.f32x2 %0, %1, %2, %3;" : "=l"(d) : "l"(a), "l"(b), "l"(c));
    return d;
}
__device__ __forceinline__ void upk2(ull v, float& x, float& y) {
    unsigned lo, hi;
    asm("mov.b64 {%0, %1}, %2;" : "=r"(lo), "=r"(hi) : "l"(v));
    x = __uint_as_float(lo); y = __uint_as_float(hi);
}

// ---------------- big GEMM: C = A[MxK] @ B[KxN], BM=128 BN=64 BK=16 -----
// 256 threads, 8x4 per thread, FFMA2 inner loop, optional split-K partials.
__global__ void gemm128(const float* __restrict__ A, const float* __restrict__ B,
                        const float* __restrict__ bias, float* __restrict__ Cfinal,
                        float* __restrict__ Cpart,
                        int M, int N, int K, int Ks, int accum)
{
    __shared__ float As[16][132];
    __shared__ float Bs[16][64];
    const int tid = threadIdx.x;
    const int z = blockIdx.z;
    const int kbeg = z * Ks;
    const int kend = min(K, kbeg + Ks);
    const int row0 = blockIdx.y * 128;
    const int col0 = blockIdx.x * 64;
    const int tx = tid & 15;        // cols: tx*4
    const int ty = tid >> 4;        // rows: ty*8
    const int akq = tid & 3;        // A loader k-quad
    const int ar  = tid >> 2;       // A loader row (0..63, +64 second)
    const int br  = tid >> 4;       // B loader k-row (0..15)
    const int bcq = tid & 15;       // B loader col-quad

    ull acc[8][2];
    #pragma unroll
    for (int r = 0; r < 8; r++) { acc[r][0] = 0ull; acc[r][1] = 0ull; }

    const int arow0 = min(row0 + ar,      M - 1);
    const int arow1 = min(row0 + ar + 64, M - 1);
    const float* Ar0 = A + (size_t)arow0 * K;
    const float* Ar1 = A + (size_t)arow1 * K;
    const bool colFast = (col0 + 63 < N);

    for (int k0 = kbeg; k0 < kend; k0 += 16) {
        // ---- load A tile (128 x 16, transposed into As[k][r]) ----
        const int ka = k0 + akq * 4;
        float4 a0, a1;
        if (ka + 3 < kend) {
            a0 = *(const float4*)(Ar0 + ka);
            a1 = *(const float4*)(Ar1 + ka);
        } else {
            a0.x = (ka+0 < kend) ? Ar0[ka+0] : 0.f;
            a0.y = (ka+1 < kend) ? Ar0[ka+1] : 0.f;
            a0.z = (ka+2 < kend) ? Ar0[ka+2] : 0.f;
            a0.w = (ka+3 < kend) ? Ar0[ka+3] : 0.f;
            a1.x = (ka+0 < kend) ? Ar1[ka+0] : 0.f;
            a1.y = (ka+1 < kend) ? Ar1[ka+1] : 0.f;
            a1.z = (ka+2 < kend) ? Ar1[ka+2] : 0.f;
            a1.w = (ka+3 < kend) ? Ar1[ka+3] : 0.f;
        }
        As[akq*4+0][ar]    = a0.x; As[akq*4+1][ar]    = a0.y;
        As[akq*4+2][ar]    = a0.z; As[akq*4+3][ar]    = a0.w;
        As[akq*4+0][ar+64] = a1.x; As[akq*4+1][ar+64] = a1.y;
        As[akq*4+2][ar+64] = a1.z; As[akq*4+3][ar+64] = a1.w;
        // ---- load B tile (16 x 64) ----
        const int kb = k0 + br;
        const int bc = col0 + bcq * 4;
        float4 bv = make_float4(0.f, 0.f, 0.f, 0.f);
        if (kb < kend) {
            const float* Bp = B + (size_t)kb * N;
            if (colFast) bv = *(const float4*)(Bp + bc);
            else {
                if (bc+0 < N) bv.x = Bp[bc+0];
                if (bc+1 < N) bv.y = Bp[bc+1];
                if (bc+2 < N) bv.z = Bp[bc+2];
                if (bc+3 < N) bv.w = Bp[bc+3];
            }
        }
        *(float4*)&Bs[br][bcq*4] = bv;
        __syncthreads();

        #pragma unroll
        for (int kk = 0; kk < 16; kk++) {
            float4 b4 = *(const float4*)&Bs[kk][tx*4];
            ull b01 = pk2(b4.x, b4.y);
            ull b23 = pk2(b4.z, b4.w);
            float4 aA = *(const float4*)&As[kk][ty*8];
            float4 aB = *(const float4*)&As[kk][ty*8+4];
            ull ad;
            ad = pk2(aA.x, aA.x); acc[0][0]=fma2(ad,b01,acc[0][0]); acc[0][1]=fma2(ad,b23,acc[0][1]);
            ad = pk2(aA.y, aA.y); acc[1][0]=fma2(ad,b01,acc[1][0]); acc[1][1]=fma2(ad,b23,acc[1][1]);
            ad = pk2(aA.z, aA.z); acc[2][0]=fma2(ad,b01,acc[2][0]); acc[2][1]=fma2(ad,b23,acc[2][1]);
            ad = pk2(aA.w, aA.w); acc[3][0]=fma2(ad,b01,acc[3][0]); acc[3][1]=fma2(ad,b23,acc[3][1]);
            ad = pk2(aB.x, aB.x); acc[4][0]=fma2(ad,b01,acc[4][0]); acc[4][1]=fma2(ad,b23,acc[4][1]);
            ad = pk2(aB.y, aB.y); acc[5][0]=fma2(ad,b01,acc[5][0]); acc[5][1]=fma2(ad,b23,acc[5][1]);
            ad = pk2(aB.z, aB.z); acc[6][0]=fma2(ad,b01,acc[6][0]); acc[6][1]=fma2(ad,b23,acc[6][1]);
            ad = pk2(aB.w, aB.w); acc[7][0]=fma2(ad,b01,acc[7][0]); acc[7][1]=fma2(ad,b23,acc[7][1]);
        }
        __syncthreads();
    }

    float* Co = (gridDim.z > 1) ? (Cpart + (size_t)z * M * N) : Cfinal;
    const int single = (gridDim.z == 1);
    #pragma unroll
    for (int r = 0; r < 8; r++) {
        const int gr = row0 + ty*8 + r;
        if (gr >= M) continue;
        float c[4];
        upk2(acc[r][0], c[0], c[1]);
        upk2(acc[r][1], c[2], c[3]);
        #pragma unroll
        for (int j = 0; j < 4; j++) {
            const int gc = col0 + tx*4 + j;
            if (gc >= N) continue;
            float v = c[j];
            if (single) {
                if (bias)  v += bias[gc];
                if (accum) v += Co[(size_t)gr * N + gc];
            }
            Co[(size_t)gr * N + gc] = v;
        }
    }
}

// ---------------- reduce split-K partials (+optional bias) --------------
__global__ void reduce_k(float* __restrict__ out, const float* __restrict__ part,
                         int lenf4, int S, const float* __restrict__ bias, int N)
{
    int i = blockIdx.x * blockDim.x + threadIdx.x;
    if (i >= lenf4) return;
    const float4* p = (const float4*)part;
    float4 v = p[i];
    for (int z = 1; z < S; z++) {
        float4 t = p[(size_t)z * lenf4 + i];
        v.x += t.x; v.y += t.y; v.z += t.z; v.w += t.w;
    }
    if (bias) {
        int col = (i * 4) % N;      // N % 4 == 0 for all uses
        v.x += bias[col+0]; v.y += bias[col+1];
        v.z += bias[col+2]; v.w += bias[col+3];
    }
    ((float4*)out)[i] = v;
}

// ---------------- gn = normalize_rows(attributes @ att_g) ----------------
__global__ void gn_kernel(const float* __restrict__ attrs,
                          const float* __restrict__ att_g,
                          float* __restrict__ gn) {
    __shared__ float s_attr[8][DATT];
    __shared__ float s_red[8][4];
    const int c0 = blockIdx.x * 8;
    const int t = threadIdx.x;       // 128
    const int lane = t & 31, warp = t >> 5;

    for (int i = t; i < 8 * DATT; i += 128) {
        int r = i / DATT, k = i - r * DATT;
        s_attr[r][k] = attrs[(size_t)(c0 + r) * DATT + k];
    }
    __syncthreads();

    float acc[8] = {0.f,0.f,0.f,0.f,0.f,0.f,0.f,0.f};
    for (int k = 0; k < DATT; k++) {
        float w = att_g[(size_t)k * HH + t];
        #pragma unroll
        for (int r = 0; r < 8; r++) acc[r] = fmaf(s_attr[r][k], w, acc[r]);
    }
    #pragma unroll
    for (int r = 0; r < 8; r++) {
        float sq = acc[r] * acc[r];
        #pragma unroll
        for (int o = 16; o; o >>= 1) sq += __shfl_xor_sync(0xffffffffu, sq, o);
        if (lane == 0) s_red[r][warp] = sq;
    }
    __syncthreads();
    #pragma unroll
    for (int r = 0; r < 8; r++) {
        float tot = s_red[r][0] + s_red[r][1] + s_red[r][2] + s_red[r][3];
        float inv = 1.f / fmaxf(sqrtf(tot), 1e-12f);
        gn[(size_t)(c0 + r) * HH + t] = acc[r] * inv;
    }
}

// ---------------- sim = gn @ gn^T, masked+scaled in epilogue ------------
// NT GEMM: 64x64 tiles, 256 threads, 4x4 per thread, K=128
__global__ void sim_kernel(const float* __restrict__ gn, float* __restrict__ out)
{
    __shared__ float As[16][68];
    __shared__ float Bs[16][68];
    const int tid = threadIdx.x;
    const int row0 = blockIdx.y * 64;
    const int col0 = blockIdx.x * 64;
    const int tx = tid & 15, ty = tid >> 4;
    const int ar = tid >> 2, akq = tid & 3;

    const float* Arp = gn + (size_t)min(row0 + ar, C_CLS - 1) * HH;
    const float* Brp = gn + (size_t)min(col0 + ar, C_CLS - 1) * HH;

    ull acc[4][2];
    #pragma unroll
    for (int r = 0; r < 4; r++) { acc[r][0] = 0ull; acc[r][1] = 0ull; }

    for (int k0 = 0; k0 < HH; k0 += 16) {
        float4 av = *(const float4*)(Arp + k0 + akq*4);
        float4 bv = *(const float4*)(Brp + k0 + akq*4);
        As[akq*4+0][ar] = av.x; As[akq*4+1][ar] = av.y;
        As[akq*4+2][ar] = av.z; As[akq*4+3][ar] = av.w;
        Bs[akq*4+0][ar] = bv.x; Bs[akq*4+1][ar] = bv.y;
        Bs[akq*4+2][ar] = bv.z; Bs[akq*4+3][ar] = bv.w;
        __syncthreads();
        #pragma unroll
        for (int kk = 0; kk < 16; kk++) {
            float4 a4 = *(const float4*)&As[kk][ty*4];
            float4 b4 = *(const float4*)&Bs[kk][tx*4];
            ull b01 = pk2(b4.x, b4.y);
            ull b23 = pk2(b4.z, b4.w);
            ull ad;
            ad = pk2(a4.x, a4.x); acc[0][0]=fma2(ad,b01,acc[0][0]); acc[0][1]=fma2(ad,b23,acc[0][1]);
            ad = pk2(a4.y, a4.y); acc[1][0]=fma2(ad,b01,acc[1][0]); acc[1][1]=fma2(ad,b23,acc[1][1]);
            ad = pk2(a4.z, a4.z); acc[2][0]=fma2(ad,b01,acc[2][0]); acc[2][1]=fma2(ad,b23,acc[2][1]);
            ad = pk2(a4.w, a4.w); acc[3][0]=fma2(ad,b01,acc[3][0]); acc[3][1]=fma2(ad,b23,acc[3][1]);
        }
        __syncthreads();
    }

    #pragma unroll
    for (int r = 0; r < 4; r++) {
        const int gr = row0 + ty*4 + r;
        if (gr >= C_CLS) continue;
        float c[4];
        upk2(acc[r][0], c[0], c[1]);
        upk2(acc[r][1], c[2], c[3]);
        #pragma unroll
        for (int j = 0; j < 4; j++) {
            const int gc = col0 + tx*4 + j;
            if (gc >= C_CLS) continue;
            float s = c[j];
            out[(size_t)gr * C_CLS + gc] = (s > THRESH) ? s * TEMP : -1e30f;
        }
    }
}

// ---------------- row softmax (in place, values pre-masked+scaled) ------
__global__ void softmax_kernel(float* __restrict__ attn)
{
    __shared__ float s_red[8];
    const int t = threadIdx.x, lane = t & 31, warp = t >> 5;
    float* row = attn + (size_t)blockIdx.x * C_CLS;

    float v[4];
    float m = -1e30f;
    #pragma unroll
    for (int i = 0; i < 4; i++) {
        int c = t + i * 256;
        v[i] = (c < C_CLS) ? row[c] : -1e30f;
        m = fmaxf(m, v[i]);
    }
    #pragma unroll
    for (int o = 16; o; o >>= 1) m = fmaxf(m, __shfl_xor_sync(0xffffffffu, m, o));
    if (lane == 0) s_red[warp] = m;
    __syncthreads();
    m = s_red[0];
    #pragma unroll
    for (int w = 1; w < 8; w++) m = fmaxf(m, s_red[w]);
    __syncthreads();

    float sum = 0.f;
    #pragma unroll
    for (int i = 0; i < 4; i++) {
        float e = (v[i] > -1e29f) ? __expf(v[i] - m) : 0.f;
        v[i] = e;
        sum += e;
    }
    #pragma unroll
    for (int o = 16; o; o >>= 1) sum += __shfl_xor_sync(0xffffffffu, sum, o);
    if (lane == 0) s_red[warp] = sum;
    __syncthreads();
    float tot = 0.f;
    #pragma unroll
    for (int w = 0; w < 8; w++) tot += s_red[w];
    float inv = 1.f / tot;
    #pragma unroll
    for (int i = 0; i < 4; i++) {
        int c = t + i * 256;
        if (c < C_CLS) row[c] = v[i] * inv;
    }
}

// ---------------- relation MLP: out[b,c] = fc_b + sum_h relu(a+p)*w -----
// 64x64 tile, 256 threads, 4x4 per thread, h processed in 2 halves of 64
__global__ void relation_kernel(const float* __restrict__ img_h,
                                const float* __restrict__ proto_h,
                                const float* __restrict__ fc_w,
                                const float* __restrict__ fc_b,
                                float* __restrict__ out)
{
    __shared__ float s_a[64][68];   // [h_local][b]
    __shared__ float s_p[64][68];   // [h_local][c]
    __shared__ float s_w[HH];
    const int tid = threadIdx.x;
    const int b0 = blockIdx.y * 64;
    const int c0 = blockIdx.x * 64;
    const int tx = tid & 15;        // c: tx*4
    const int ty = tid >> 4;        // b: ty*4
    const int bl = tid >> 2;        // loader row (0..63)
    const int hq = tid & 3;         // loader h-quad group

    if (tid < HH) s_w[tid] = fc_w[tid];

    float acc[4][4];
    #pragma unroll
    for (int i = 0; i < 4; i++)
        #pragma unroll
        for (int j = 0; j < 4; j++) acc[i][j] = 0.f;

    const float* arow = img_h   + (size_t)(b0 + bl) * HH;
    const float* prow = proto_h + (size_t)min(c0 + bl, C_CLS - 1) * HH;

    for (int h0 = 0; h0 < HH; h0 += 64) {
        #pragma unroll
        for (int it = 0; it < 4; it++) {
            const int hh = (hq + 4*it) * 4;      // 0..60
            float4 va = *(const float4*)(arow + h0 + hh);
            float4 vp = *(const float4*)(prow + h0 + hh);
            s_a[hh+0][bl] = va.x; s_a[hh+1][bl] = va.y;
            s_a[hh+2][bl] = va.z; s_a[hh+3][bl] = va.w;
            s_p[hh+0][bl] = vp.x; s_p[hh+1][bl] = vp.y;
            s_p[hh+2][bl] = vp.z; s_p[hh+3][bl] = vp.w;
        }
        __syncthreads();
        #pragma unroll 8
        for (int hh = 0; hh < 64; hh++) {
            const float w = s_w[h0 + hh];
            float4 a4 = *(const float4*)&s_a[hh][ty*4];
            float4 p4 = *(const float4*)&s_p[hh][tx*4];
            const float a[4] = {a4.x, a4.y, a4.z, a4.w};
            const float p[4] = {p4.x, p4.y, p4.z, p4.w};
            #pragma unroll
            for (int i = 0; i < 4; i++)
                #pragma unroll
                for (int j = 0; j < 4; j++)
                    acc[i][j] = fmaf(fmaxf(a[i] + p[j], 0.f), w, acc[i][j]);
        }
        __syncthreads();
    }

    const float bias = fc_b[0];
    #pragma unroll
    for (int i = 0; i < 4; i++) {
        const int b = b0 + ty*4 + i;             // BB % 64 == 0, always valid
        #pragma unroll
        for (int j = 0; j < 4; j++) {
            const int c = c0 + tx*4 + j;
            if (c < C_CLS) out[(size_t)b * C_CLS + c] = acc[i][j] + bias;
        }
    }
}

// ---------------- host launch ----------------
extern "C" void kernel_launch(void* const* d_in, const int* in_sizes, int n_in,
                              void* d_out, int out_size) {
    const float* image_feats = (const float*)d_in[0];  // [2048,2048]
    const float* img_proto   = (const float*)d_in[1];  // [1000,2048]
    const float* attributes  = (const float*)d_in[2];  // [1000,312]
    const float* att_g   = (const float*)d_in[4];      // [312,128]
    const float* slim_w  = (const float*)d_in[5];      // [2048,312]
    const float* slim_b  = (const float*)d_in[6];      // [312]
    const float* img_w   = (const float*)d_in[7];      // [2048,128]
    const float* proto_w = (const float*)d_in[8];      // [624,128]
    const float* proto_b = (const float*)d_in[9];      // [1,128]
    const float* fc_w    = (const float*)d_in[10];     // [128,1]
    const float* fc_b    = (const float*)d_in[11];     // [1]
    float* out = (float*)d_out;

    float *proto_red, *gnp, *attnp, *Mp, *proto_hp, *img_hp, *scr;
    cudaGetSymbolAddress((void**)&proto_red, g_proto_red);
    cudaGetSymbolAddress((void**)&gnp,       g_gn);
    cudaGetSymbolAddress((void**)&attnp,     g_attn);
    cudaGetSymbolAddress((void**)&Mp,        g_M);
    cudaGetSymbolAddress((void**)&proto_hp,  g_proto_h);
    cudaGetSymbolAddress((void**)&img_hp,    g_img_h);
    cudaGetSymbolAddress((void**)&scr,       g_scratch);

    // img_h = image_feats @ img_w  (split-K 4)        [2048,128]
    gemm128<<<dim3(2, 16, 4), 256>>>(image_feats, img_w, nullptr, scr, scr,
                                     BB, HH, DIMG, 512, 0);
    reduce_k<<<(BB*HH/4 + 255)/256, 256>>>(img_hp, scr, BB*HH/4, 4, nullptr, HH);

    // proto_red = img_proto @ slim_w + slim_b (split-K 4)   [1000,312]
    gemm128<<<dim3(5, 8, 4), 256>>>(img_proto, slim_w, nullptr, scr, scr,
                                    C_CLS, DATT, DIMG, 512, 0);
    reduce_k<<<(C_CLS*DATT/4 + 255)/256, 256>>>(proto_red, scr, C_CLS*DATT/4, 4, slim_b, DATT);

    // gn = normalize_rows(attributes @ att_g)         [1000,128]
    gn_kernel<<<C_CLS / 8, 128>>>(attributes, att_g, gnp);

    // sim (masked+scaled) = mask(gn@gn^T)*T           [1000,1000]
    sim_kernel<<<dim3(16, 16), 256>>>(gnp, attnp);

    // attn = softmax rows (in place)
    softmax_kernel<<<C_CLS, 256>>>(attnp);

    // M = attributes @ proto_w_top + proto_red @ proto_w_bot + proto_b  [1000,128]
    gemm128<<<dim3(2, 8, 1), 256>>>(attributes, proto_w, nullptr, Mp, Mp,
                                    C_CLS, HH, DATT, DATT, 0);
    gemm128<<<dim3(2, 8, 1), 256>>>(proto_red, proto_w + (size_t)DATT * HH, proto_b, Mp, Mp,
                                    C_CLS, HH, DATT, DATT, 1);

    // proto_h = attn @ M  (split-K 2; proto_b already folded: rows of attn sum to 1)
    gemm128<<<dim3(2, 8, 2), 256>>>(attnp, Mp, nullptr, scr, scr,
                                    C_CLS, HH, C_CLS, 500, 0);
    reduce_k<<<(C_CLS*HH/4 + 255)/256, 256>>>(proto_hp, scr, C_CLS*HH/4, 2, nullptr, HH);

    // out[b,c] = fc_b + relu(img_h[b]+proto_h[c]) . fc_w
    relation_kernel<<<dim3(16, 32), 256>>>(img_hp, proto_hp, fc_w, fc_b, out);
}

// round 3
// speedup vs baseline: 2.6928x; 1.1185x over previous
#include <cuda_runtime.h>
#include <math.h>

// ---------------- problem constants ----------------
#define C_CLS   1000
#define DIMG    2048
#define DATT    312
#define HH      128
#define BB      2048
#define THRESH  0.76604444311897803f   // cos(40 deg)
#define TEMP    32.0f

typedef unsigned long long ull;

// ---------------- scratch (device globals; no allocation allowed) -------
__device__ float g_proto_red[C_CLS * DATT];        // [1000,312]
__device__ float g_gn[C_CLS * HH];                 // [1000,128]
__device__ float g_attn[C_CLS * C_CLS];            // [1000,1000]
__device__ float g_M[C_CLS * HH];                  // [1000,128] (proto_b folded)
__device__ float g_proto_h[C_CLS * HH];            // [1000,128]
__device__ float g_img_h[BB * HH];                 // [2048,128]
__device__ float g_scr_a[4 * C_CLS * DATT];        // proto_red / proto_h partials
__device__ float g_scr_b[4 * BB * HH];             // img_h partials

// ---------------- packed f32x2 helpers ----------------
__device__ __forceinline__ ull pk2(float x, float y) {
    ull r;
    asm("mov.b64 %0, {%1, %2};" : "=l"(r) : "r"(__float_as_uint(x)), "r"(__float_as_uint(y)));
    return r;
}
__device__ __forceinline__ ull fma2(ull a, ull b, ull c) {
    ull d;
    asm("fma.rn.f32x2 %0, %1, %2, %3;" : "=l"(d) : "l"(a), "l"(b), "l"(c));
    return d;
}
__device__ __forceinline__ ull add2(ull a, ull b) {
    ull d;
    asm("add.rn.f32x2 %0, %1, %2;" : "=l"(d) : "l"(a), "l"(b));
    return d;
}
__device__ __forceinline__ void upk2(ull v, float& x, float& y) {
    unsigned lo, hi;
    asm("mov.b64 {%0, %1}, %2;" : "=r"(lo), "=r"(hi) : "l"(v));
    x = __uint_as_float(lo); y = __uint_as_float(hi);
}

// ---------------- big GEMM: C = A[MxK] @ B[KxN], BM=128 BN=64 BK=16 -----
// 256 threads, 8x4 per thread. A stored DUPLICATED in smem so the inner loop
// is pure LDS.128 -> FFMA2 (no packing MOVs). Optional split-K partials.
__global__ void gemm128(const float* __restrict__ A, const float* __restrict__ B,
                        const float* __restrict__ bias, float* __restrict__ Cfinal,
                        float* __restrict__ Cpart,
                        int M, int N, int K, int Ks, int accum)
{
    __shared__ __align__(16) float As2[16][268];   // duplicated pairs: 256 used + pad
    __shared__ __align__(16) float Bs[16][64];
    const int tid = threadIdx.x;
    const int z = blockIdx.z;
    const int kbeg = z * Ks;                        // Ks must be multiple of 4
    const int kend = min(K, kbeg + Ks);
    const int row0 = blockIdx.y * 128;
    const int col0 = blockIdx.x * 64;
    const int tx = tid & 15;        // cols: tx*4
    const int ty = tid >> 4;        // rows: ty*8
    const int akq = tid & 3;        // A loader k-quad
    const int ar  = tid >> 2;       // A loader row (0..63, +64 second)
    const int br  = tid >> 4;       // B loader k-row (0..15)
    const int bcq = tid & 15;       // B loader col-quad

    ull acc[8][2];
    #pragma unroll
    for (int r = 0; r < 8; r++) { acc[r][0] = 0ull; acc[r][1] = 0ull; }

    const int arow0 = min(row0 + ar,      M - 1);
    const int arow1 = min(row0 + ar + 64, M - 1);
    const float* Ar0 = A + (size_t)arow0 * K;
    const float* Ar1 = A + (size_t)arow1 * K;
    const bool colFast = (col0 + 63 < N);

    for (int k0 = kbeg; k0 < kend; k0 += 16) {
        // ---- load A tile (128 x 16), store duplicated pairs ----
        const int ka = k0 + akq * 4;
        float4 a0, a1;
        if (ka + 3 < kend) {
            a0 = *(const float4*)(Ar0 + ka);
            a1 = *(const float4*)(Ar1 + ka);
        } else {
            a0.x = (ka+0 < kend) ? Ar0[ka+0] : 0.f;
            a0.y = (ka+1 < kend) ? Ar0[ka+1] : 0.f;
            a0.z = (ka+2 < kend) ? Ar0[ka+2] : 0.f;
            a0.w = (ka+3 < kend) ? Ar0[ka+3] : 0.f;
            a1.x = (ka+0 < kend) ? Ar1[ka+0] : 0.f;
            a1.y = (ka+1 < kend) ? Ar1[ka+1] : 0.f;
            a1.z = (ka+2 < kend) ? Ar1[ka+2] : 0.f;
            a1.w = (ka+3 < kend) ? Ar1[ka+3] : 0.f;
        }
        *(float2*)&As2[akq*4+0][2*ar]        = make_float2(a0.x, a0.x);
        *(float2*)&As2[akq*4+1][2*ar]        = make_float2(a0.y, a0.y);
        *(float2*)&As2[akq*4+2][2*ar]        = make_float2(a0.z, a0.z);
        *(float2*)&As2[akq*4+3][2*ar]        = make_float2(a0.w, a0.w);
        *(float2*)&As2[akq*4+0][2*(ar+64)]   = make_float2(a1.x, a1.x);
        *(float2*)&As2[akq*4+1][2*(ar+64)]   = make_float2(a1.y, a1.y);
        *(float2*)&As2[akq*4+2][2*(ar+64)]   = make_float2(a1.z, a1.z);
        *(float2*)&As2[akq*4+3][2*(ar+64)]   = make_float2(a1.w, a1.w);
        // ---- load B tile (16 x 64) ----
        const int kb = k0 + br;
        const int bc = col0 + bcq * 4;
        float4 bv = make_float4(0.f, 0.f, 0.f, 0.f);
        if (kb < kend) {
            const float* Bp = B + (size_t)kb * N;
            if (colFast) bv = *(const float4*)(Bp + bc);
            else {
                if (bc+0 < N) bv.x = Bp[bc+0];
                if (bc+1 < N) bv.y = Bp[bc+1];
                if (bc+2 < N) bv.z = Bp[bc+2];
                if (bc+3 < N) bv.w = Bp[bc+3];
            }
        }
        *(float4*)&Bs[br][bcq*4] = bv;
        __syncthreads();

        #pragma unroll
        for (int kk = 0; kk < 16; kk++) {
            ulonglong2 bq  = *(const ulonglong2*)&Bs[kk][tx*4];     // (b0,b1),(b2,b3)
            ulonglong2 a01 = *(const ulonglong2*)&As2[kk][ty*16];   // (a0,a0),(a1,a1)
            ulonglong2 a23 = *(const ulonglong2*)&As2[kk][ty*16+4];
            ulonglong2 a45 = *(const ulonglong2*)&As2[kk][ty*16+8];
            ulonglong2 a67 = *(const ulonglong2*)&As2[kk][ty*16+12];
            acc[0][0]=fma2(a01.x,bq.x,acc[0][0]); acc[0][1]=fma2(a01.x,bq.y,acc[0][1]);
            acc[1][0]=fma2(a01.y,bq.x,acc[1][0]); acc[1][1]=fma2(a01.y,bq.y,acc[1][1]);
            acc[2][0]=fma2(a23.x,bq.x,acc[2][0]); acc[2][1]=fma2(a23.x,bq.y,acc[2][1]);
            acc[3][0]=fma2(a23.y,bq.x,acc[3][0]); acc[3][1]=fma2(a23.y,bq.y,acc[3][1]);
            acc[4][0]=fma2(a45.x,bq.x,acc[4][0]); acc[4][1]=fma2(a45.x,bq.y,acc[4][1]);
            acc[5][0]=fma2(a45.y,bq.x,acc[5][0]); acc[5][1]=fma2(a45.y,bq.y,acc[5][1]);
            acc[6][0]=fma2(a67.x,bq.x,acc[6][0]); acc[6][1]=fma2(a67.x,bq.y,acc[6][1]);
            acc[7][0]=fma2(a67.y,bq.x,acc[7][0]); acc[7][1]=fma2(a67.y,bq.y,acc[7][1]);
        }
        __syncthreads();
    }

    float* Co = (gridDim.z > 1) ? (Cpart + (size_t)z * M * N) : Cfinal;
    const int single = (gridDim.z == 1);
    #pragma unroll
    for (int r = 0; r < 8; r++) {
        const int gr = row0 + ty*8 + r;
        if (gr >= M) continue;
        float c[4];
        upk2(acc[r][0], c[0], c[1]);
        upk2(acc[r][1], c[2], c[3]);
        #pragma unroll
        for (int j = 0; j < 4; j++) {
            const int gc = col0 + tx*4 + j;
            if (gc >= N) continue;
            float v = c[j];
            if (single) {
                if (bias)  v += bias[gc];
                if (accum) v += Co[(size_t)gr * N + gc];
            }
            Co[(size_t)gr * N + gc] = v;
        }
    }
}

// ---------------- reduce split-K partials (+optional bias) --------------
__global__ void reduce_k(float* __restrict__ out, const float* __restrict__ part,
                         int lenf4, int S, const float* __restrict__ bias, int N)
{
    int i = blockIdx.x * blockDim.x + threadIdx.x;
    if (i >= lenf4) return;
    const float4* p = (const float4*)part;
    float4 acc = p[i];
    float4 t[3];
    #pragma unroll
    for (int z = 1; z < 4; z++)
        if (z < S) t[z-1] = p[(size_t)z * lenf4 + i];
    #pragma unroll
    for (int z = 1; z < 4; z++)
        if (z < S) { acc.x += t[z-1].x; acc.y += t[z-1].y; acc.z += t[z-1].z; acc.w += t[z-1].w; }
    if (bias) {
        int col = (i * 4) % N;      // N % 4 == 0 for all uses
        acc.x += bias[col+0]; acc.y += bias[col+1];
        acc.z += bias[col+2]; acc.w += bias[col+3];
    }
    ((float4*)out)[i] = acc;
}

// ---------------- gn = normalize_rows(attributes @ att_g) ----------------
__global__ void gn_kernel(const float* __restrict__ attrs,
                          const float* __restrict__ att_g,
                          float* __restrict__ gn) {
    __shared__ float s_attr[8][DATT];
    __shared__ float s_red[8][4];
    const int c0 = blockIdx.x * 8;
    const int t = threadIdx.x;       // 128
    const int lane = t & 31, warp = t >> 5;

    for (int i = t; i < 8 * DATT; i += 128) {
        int r = i / DATT, k = i - r * DATT;
        s_attr[r][k] = attrs[(size_t)(c0 + r) * DATT + k];
    }
    __syncthreads();

    float acc[8] = {0.f,0.f,0.f,0.f,0.f,0.f,0.f,0.f};
    for (int k = 0; k < DATT; k++) {
        float w = att_g[(size_t)k * HH + t];
        #pragma unroll
        for (int r = 0; r < 8; r++) acc[r] = fmaf(s_attr[r][k], w, acc[r]);
    }
    #pragma unroll
    for (int r = 0; r < 8; r++) {
        float sq = acc[r] * acc[r];
        #pragma unroll
        for (int o = 16; o; o >>= 1) sq += __shfl_xor_sync(0xffffffffu, sq, o);
        if (lane == 0) s_red[r][warp] = sq;
    }
    __syncthreads();
    #pragma unroll
    for (int r = 0; r < 8; r++) {
        float tot = s_red[r][0] + s_red[r][1] + s_red[r][2] + s_red[r][3];
        float inv = 1.f / fmaxf(sqrtf(tot), 1e-12f);
        gn[(size_t)(c0 + r) * HH + t] = acc[r] * inv;
    }
}

// ---------------- sim = gn @ gn^T, masked+scaled in epilogue ------------
// NT GEMM: 64x64 tiles, 256 threads, 4x4 per thread, K=128; duplicated A smem
__global__ void sim_kernel(const float* __restrict__ gn, float* __restrict__ out)
{
    __shared__ __align__(16) float As2[16][140];   // duplicated pairs: 128 used
    __shared__ __align__(16) float Bs[16][68];
    const int tid = threadIdx.x;
    const int row0 = blockIdx.y * 64;
    const int col0 = blockIdx.x * 64;
    const int tx = tid & 15, ty = tid >> 4;
    const int ar = tid >> 2, akq = tid & 3;

    const float* Arp = gn + (size_t)min(row0 + ar, C_CLS - 1) * HH;
    const float* Brp = gn + (size_t)min(col0 + ar, C_CLS - 1) * HH;

    ull acc[4][2];
    #pragma unroll
    for (int r = 0; r < 4; r++) { acc[r][0] = 0ull; acc[r][1] = 0ull; }

    for (int k0 = 0; k0 < HH; k0 += 16) {
        float4 av = *(const float4*)(Arp + k0 + akq*4);
        float4 bv = *(const float4*)(Brp + k0 + akq*4);
        *(float2*)&As2[akq*4+0][2*ar] = make_float2(av.x, av.x);
        *(float2*)&As2[akq*4+1][2*ar] = make_float2(av.y, av.y);
        *(float2*)&As2[akq*4+2][2*ar] = make_float2(av.z, av.z);
        *(float2*)&As2[akq*4+3][2*ar] = make_float2(av.w, av.w);
        Bs[akq*4+0][ar] = bv.x; Bs[akq*4+1][ar] = bv.y;
        Bs[akq*4+2][ar] = bv.z; Bs[akq*4+3][ar] = bv.w;
        __syncthreads();
        #pragma unroll
        for (int kk = 0; kk < 16; kk++) {
            ulonglong2 bq  = *(const ulonglong2*)&Bs[kk][tx*4];
            ulonglong2 a01 = *(const ulonglong2*)&As2[kk][ty*8];
            ulonglong2 a23 = *(const ulonglong2*)&As2[kk][ty*8+4];
            acc[0][0]=fma2(a01.x,bq.x,acc[0][0]); acc[0][1]=fma2(a01.x,bq.y,acc[0][1]);
            acc[1][0]=fma2(a01.y,bq.x,acc[1][0]); acc[1][1]=fma2(a01.y,bq.y,acc[1][1]);
            acc[2][0]=fma2(a23.x,bq.x,acc[2][0]); acc[2][1]=fma2(a23.x,bq.y,acc[2][1]);
            acc[3][0]=fma2(a23.y,bq.x,acc[3][0]); acc[3][1]=fma2(a23.y,bq.y,acc[3][1]);
        }
        __syncthreads();
    }

    #pragma unroll
    for (int r = 0; r < 4; r++) {
        const int gr = row0 + ty*4 + r;
        if (gr >= C_CLS) continue;
        float c[4];
        upk2(acc[r][0], c[0], c[1]);
        upk2(acc[r][1], c[2], c[3]);
        #pragma unroll
        for (int j = 0; j < 4; j++) {
            const int gc = col0 + tx*4 + j;
            if (gc >= C_CLS) continue;
            float s = c[j];
            out[(size_t)gr * C_CLS + gc] = (s > THRESH) ? s * TEMP : -1e30f;
        }
    }
}

// ---------------- row softmax (in place, values pre-masked+scaled) ------
__global__ void softmax_kernel(float* __restrict__ attn)
{
    __shared__ float s_red[8];
    const int t = threadIdx.x, lane = t & 31, warp = t >> 5;
    float* row = attn + (size_t)blockIdx.x * C_CLS;

    float v[4];
    float m = -1e30f;
    #pragma unroll
    for (int i = 0; i < 4; i++) {
        int c = t + i * 256;
        v[i] = (c < C_CLS) ? row[c] : -1e30f;
        m = fmaxf(m, v[i]);
    }
    #pragma unroll
    for (int o = 16; o; o >>= 1) m = fmaxf(m, __shfl_xor_sync(0xffffffffu, m, o));
    if (lane == 0) s_red[warp] = m;
    __syncthreads();
    m = s_red[0];
    #pragma unroll
    for (int w = 1; w < 8; w++) m = fmaxf(m, s_red[w]);
    __syncthreads();

    float sum = 0.f;
    #pragma unroll
    for (int i = 0; i < 4; i++) {
        float e = (v[i] > -1e29f) ? __expf(v[i] - m) : 0.f;
        v[i] = e;
        sum += e;
    }
    #pragma unroll
    for (int o = 16; o; o >>= 1) sum += __shfl_xor_sync(0xffffffffu, sum, o);
    if (lane == 0) s_red[warp] = sum;
    __syncthreads();
    float tot = 0.f;
    #pragma unroll
    for (int w = 0; w < 8; w++) tot += s_red[w];
    float inv = 1.f / tot;
    #pragma unroll
    for (int i = 0; i < 4; i++) {
        int c = t + i * 256;
        if (c < C_CLS) row[c] = v[i] * inv;
    }
}

// ---------------- relation MLP: out[b,c] = fc_b + sum_h relu(a+p)*w -----
// 64x64 tile, 256 threads, 4x4/thread; packed f32x2 add+fma, scalar relu
__global__ void relation_kernel(const float* __restrict__ img_h,
                                const float* __restrict__ proto_h,
                                const float* __restrict__ fc_w,
                                const float* __restrict__ fc_b,
                                float* __restrict__ out)
{
    __shared__ __align__(16) float s_a2[64][136];  // [h][2*b] duplicated
    __shared__ __align__(16) float s_p[64][68];    // [h][c]
    __shared__ __align__(16) float s_w2[2 * HH];   // duplicated weights
    const int tid = threadIdx.x;
    const int b0 = blockIdx.y * 64;
    const int c0 = blockIdx.x * 64;
    const int tx = tid & 15;        // c: tx*4
    const int ty = tid >> 4;        // b: ty*4
    const int bl = tid >> 2;        // loader row (0..63)
    const int hq = tid & 3;         // loader h-quad group

    if (tid < HH) { float w = fc_w[tid]; s_w2[2*tid] = w; s_w2[2*tid+1] = w; }

    ull acc[4][2];
    #pragma unroll
    for (int i = 0; i < 4; i++) { acc[i][0] = 0ull; acc[i][1] = 0ull; }

    const float* arow = img_h   + (size_t)(b0 + bl) * HH;
    const float* prow = proto_h + (size_t)min(c0 + bl, C_CLS - 1) * HH;

    for (int h0 = 0; h0 < HH; h0 += 64) {
        #pragma unroll
        for (int it = 0; it < 4; it++) {
            const int hh = (hq + 4*it) * 4;      // 0..60
            float4 va = *(const float4*)(arow + h0 + hh);
            float4 vp = *(const float4*)(prow + h0 + hh);
            *(float2*)&s_a2[hh+0][2*bl] = make_float2(va.x, va.x);
            *(float2*)&s_a2[hh+1][2*bl] = make_float2(va.y, va.y);
            *(float2*)&s_a2[hh+2][2*bl] = make_float2(va.z, va.z);
            *(float2*)&s_a2[hh+3][2*bl] = make_float2(va.w, va.w);
            s_p[hh+0][bl] = vp.x; s_p[hh+1][bl] = vp.y;
            s_p[hh+2][bl] = vp.z; s_p[hh+3][bl] = vp.w;
        }
        __syncthreads();
        #pragma unroll 4
        for (int hh = 0; hh < 64; hh++) {
            ull w2 = *(const ull*)&s_w2[2*(h0 + hh)];
            ulonglong2 aA = *(const ulonglong2*)&s_a2[hh][ty*8];     // (a0,a0),(a1,a1)
            ulonglong2 aB = *(const ulonglong2*)&s_a2[hh][ty*8+4];   // (a2,a2),(a3,a3)
            ulonglong2 pv = *(const ulonglong2*)&s_p[hh][tx*4];      // (p0,p1),(p2,p3)
            ull av[4] = {aA.x, aA.y, aB.x, aB.y};
            #pragma unroll
            for (int i = 0; i < 4; i++) {
                #pragma unroll
                for (int jp = 0; jp < 2; jp++) {
                    ull t = add2(av[i], jp ? pv.y : pv.x);
                    float t0, t1;
                    upk2(t, t0, t1);
                    t = pk2(fmaxf(t0, 0.f), fmaxf(t1, 0.f));
                    acc[i][jp] = fma2(t, w2, acc[i][jp]);
                }
            }
        }
        __syncthreads();
    }

    const float bias = fc_b[0];
    #pragma unroll
    for (int i = 0; i < 4; i++) {
        const int b = b0 + ty*4 + i;             // BB % 64 == 0, always valid
        float c[4];
        upk2(acc[i][0], c[0], c[1]);
        upk2(acc[i][1], c[2], c[3]);
        const int cc = c0 + tx*4;
        if (cc + 3 < C_CLS) {
            float4 v = make_float4(c[0] + bias, c[1] + bias, c[2] + bias, c[3] + bias);
            *(float4*)&out[(size_t)b * C_CLS + cc] = v;
        } else {
            #pragma unroll
            for (int j = 0; j < 4; j++)
                if (cc + j < C_CLS) out[(size_t)b * C_CLS + cc + j] = c[j] + bias;
        }
    }
}

// ---------------- host launch ----------------
extern "C" void kernel_launch(void* const* d_in, const int* in_sizes, int n_in,
                              void* d_out, int out_size) {
    const float* image_feats = (const float*)d_in[0];  // [2048,2048]
    const float* img_proto   = (const float*)d_in[1];  // [1000,2048]
    const float* attributes  = (const float*)d_in[2];  // [1000,312]
    const float* att_g   = (const float*)d_in[4];      // [312,128]
    const float* slim_w  = (const float*)d_in[5];      // [2048,312]
    const float* slim_b  = (const float*)d_in[6];      // [312]
    const float* img_w   = (const float*)d_in[7];      // [2048,128]
    const float* proto_w = (const float*)d_in[8];      // [624,128]
    const float* proto_b = (const float*)d_in[9];      // [1,128]
    const float* fc_w    = (const float*)d_in[10];     // [128,1]
    const float* fc_b    = (const float*)d_in[11];     // [1]
    float* out = (float*)d_out;

    float *proto_red, *gnp, *attnp, *Mp, *proto_hp, *img_hp, *scrA, *scrB;
    cudaGetSymbolAddress((void**)&proto_red, g_proto_red);
    cudaGetSymbolAddress((void**)&gnp,       g_gn);
    cudaGetSymbolAddress((void**)&attnp,     g_attn);
    cudaGetSymbolAddress((void**)&Mp,        g_M);
    cudaGetSymbolAddress((void**)&proto_hp,  g_proto_h);
    cudaGetSymbolAddress((void**)&img_hp,    g_img_h);
    cudaGetSymbolAddress((void**)&scrA,      g_scr_a);
    cudaGetSymbolAddress((void**)&scrB,      g_scr_b);

    // one-time stream/event setup (resource init only; per-call work identical)
    static cudaStream_t s1 = nullptr, s2 = nullptr;
    static cudaEvent_t ev0 = nullptr, ev1 = nullptr, ev2 = nullptr;
    if (!s1) {
        cudaStreamCreateWithFlags(&s1, cudaStreamNonBlocking);
        cudaStreamCreateWithFlags(&s2, cudaStreamNonBlocking);
        cudaEventCreateWithFlags(&ev0, cudaEventDisableTiming);
        cudaEventCreateWithFlags(&ev1, cudaEventDisableTiming);
        cudaEventCreateWithFlags(&ev2, cudaEventDisableTiming);
    }
    cudaStream_t s0 = 0;  // legacy default (the captured stream)

    // fork
    cudaEventRecord(ev0, s0);
    cudaStreamWaitEvent(s1, ev0, 0);
    cudaStreamWaitEvent(s2, ev0, 0);

    // ---- chain C (s1): gn -> sim -> softmax --------------------------------
    gn_kernel<<<C_CLS / 8, 128, 0, s1>>>(attributes, att_g, gnp);
    sim_kernel<<<dim3(16, 16), 256, 0, s1>>>(gnp, attnp);
    softmax_kernel<<<C_CLS, 256, 0, s1>>>(attnp);
    cudaEventRecord(ev1, s1);

    // ---- chain A (s2): img_h = image_feats @ img_w (split-K 4) -------------
    gemm128<<<dim3(2, 16, 4), 256, 0, s2>>>(image_feats, img_w, nullptr, scrB, scrB,
                                            BB, HH, DIMG, 512, 0);
    reduce_k<<<(BB*HH/4 + 255)/256, 256, 0, s2>>>(img_hp, scrB, BB*HH/4, 4, nullptr, HH);
    cudaEventRecord(ev2, s2);

    // ---- chain B (s0): proto_red -> M --------------------------------------
    // M_top = attributes @ proto_w[0:312]
    gemm128<<<dim3(2, 8, 1), 256, 0, s0>>>(attributes, proto_w, nullptr, Mp, Mp,
                                           C_CLS, HH, DATT, DATT, 0);
    // proto_red = img_proto @ slim_w + slim_b (split-K 4)
    gemm128<<<dim3(5, 8, 4), 256, 0, s0>>>(img_proto, slim_w, nullptr, scrA, scrA,
                                           C_CLS, DATT, DIMG, 512, 0);
    reduce_k<<<(C_CLS*DATT/4 + 255)/256, 256, 0, s0>>>(proto_red, scrA, C_CLS*DATT/4, 4, slim_b, DATT);
    // M += proto_red @ proto_w[312:624] + proto_b
    gemm128<<<dim3(2, 8, 1), 256, 0, s0>>>(proto_red, proto_w + (size_t)DATT * HH, proto_b, Mp, Mp,
                                           C_CLS, HH, DATT, DATT, 1);

    // ---- join: proto_h = attn @ M (split-K 4; proto_b folded via row-sum=1)
    cudaStreamWaitEvent(s0, ev1, 0);
    gemm128<<<dim3(2, 8, 4), 256, 0, s0>>>(attnp, Mp, nullptr, scrA, scrA,
                                           C_CLS, HH, C_CLS, 256, 0);
    reduce_k<<<(C_CLS*HH/4 + 255)/256, 256, 0, s0>>>(proto_hp, scrA, C_CLS*HH/4, 4, nullptr, HH);

    // ---- join: relation ----------------------------------------------------
    cudaStreamWaitEvent(s0, ev2, 0);
    relation_kernel<<<dim3(16, 32), 256, 0, s0>>>(img_hp, proto_hp, fc_w, fc_b, out);
}

// round 5
// speedup vs baseline: 4.4906x; 1.6676x over previous
#include <cuda_runtime.h>
#include <math.h>

// ---------------- problem constants ----------------
#define C_CLS   1000
#define DIMG    2048
#define DATT    312
#define HH      128
#define BB      2048
#define THRESH  0.76604444311897803f   // cos(40 deg)
#define TEMP    32.0f

typedef unsigned long long ull;

// ---------------- scratch (device globals; no allocation allowed) -------
__device__ float g_proto_red[C_CLS * DATT];        // [1000,312]
__device__ float g_gn[C_CLS * HH];                 // [1000,128]
__device__ float g_attn[C_CLS * C_CLS];            // [1000,1000]
__device__ float g_M[C_CLS * HH];                  // [1000,128]
__device__ float g_proto_h[C_CLS * HH];            // [1000,128]
__device__ float g_img_h[BB * HH];                 // [2048,128]
__device__ float g_scr_a[8 * C_CLS * DATT];        // proto_red / proto_h partials
__device__ float g_scr_b[8 * BB * HH];             // img_h partials
__device__ float g_scr_m[4 * C_CLS * HH];          // M partials

// ---------------- packed f32x2 helpers ----------------
__device__ __forceinline__ ull pk2(float x, float y) {
    ull r;
    asm("mov.b64 %0, {%1, %2};" : "=l"(r) : "r"(__float_as_uint(x)), "r"(__float_as_uint(y)));
    return r;
}
__device__ __forceinline__ ull fma2(ull a, ull b, ull c) {
    ull d;
    asm("fma.rn.f32x2 %0, %1, %2, %3;" : "=l"(d) : "l"(a), "l"(b), "l"(c));
    return d;
}
__device__ __forceinline__ ull add2(ull a, ull b) {
    ull d;
    asm("add.rn.f32x2 %0, %1, %2;" : "=l"(d) : "l"(a), "l"(b));
    return d;
}
__device__ __forceinline__ void upk2(ull v, float& x, float& y) {
    unsigned lo, hi;
    asm("mov.b64 {%0, %1}, %2;" : "=r"(lo), "=r"(hi) : "l"(v));
    x = __uint_as_float(lo); y = __uint_as_float(hi);
}

// ---------------- big GEMM: C = A[MxK] @ B[KxN], BM=128 BN=64 BK=16 -----
// 256 threads, 8x4/thread, FFMA2 inner loop (A duplicated in smem),
// double-buffered through registers (LDG for tile t+1 issued before compute t).
__global__ void __launch_bounds__(256, 2)
gemm128(const float* __restrict__ A, const float* __restrict__ B,
        float* __restrict__ Cpart, int M, int N, int K, int Ks)
{
    __shared__ __align__(16) float As2[16][268];   // duplicated pairs
    __shared__ __align__(16) float Bs[16][64];
    const int tid = threadIdx.x;
    const int z = blockIdx.z;
    const int kbeg = z * Ks;                        // Ks multiple of 4
    const int kend = min(K, kbeg + Ks);
    const int row0 = blockIdx.y * 128;
    const int col0 = blockIdx.x * 64;
    const int tx = tid & 15;        // cols: tx*4
    const int ty = tid >> 4;        // rows: ty*8
    const int akq = tid & 3;        // A loader k-quad
    const int ar  = tid >> 2;       // A loader row (0..63, +64 second)
    const int br  = tid >> 4;       // B loader k-row (0..15)
    const int bcq = tid & 15;       // B loader col-quad

    ull acc[8][2];
    #pragma unroll
    for (int r = 0; r < 8; r++) { acc[r][0] = 0ull; acc[r][1] = 0ull; }

    const int arow0 = min(row0 + ar,      M - 1);
    const int arow1 = min(row0 + ar + 64, M - 1);
    const float* Ar0 = A + (size_t)arow0 * K;
    const float* Ar1 = A + (size_t)arow1 * K;
    const bool colFast = (col0 + 63 < N);

    float4 sa0, sa1, sb;   // staging registers

    auto loadTile = [&](int kb) {
        const int ka = kb + akq * 4;
        if (ka + 3 < kend) {
            sa0 = *(const float4*)(Ar0 + ka);
            sa1 = *(const float4*)(Ar1 + ka);
        } else {
            sa0.x = (ka+0 < kend) ? Ar0[ka+0] : 0.f;
            sa0.y = (ka+1 < kend) ? Ar0[ka+1] : 0.f;
            sa0.z = (ka+2 < kend) ? Ar0[ka+2] : 0.f;
            sa0.w = (ka+3 < kend) ? Ar0[ka+3] : 0.f;
            sa1.x = (ka+0 < kend) ? Ar1[ka+0] : 0.f;
            sa1.y = (ka+1 < kend) ? Ar1[ka+1] : 0.f;
            sa1.z = (ka+2 < kend) ? Ar1[ka+2] : 0.f;
            sa1.w = (ka+3 < kend) ? Ar1[ka+3] : 0.f;
        }
        const int kb2 = kb + br;
        const int bc = col0 + bcq * 4;
        sb = make_float4(0.f, 0.f, 0.f, 0.f);
        if (kb2 < kend) {
            const float* Bp = B + (size_t)kb2 * N;
            if (colFast) sb = *(const float4*)(Bp + bc);
            else {
                if (bc+0 < N) sb.x = Bp[bc+0];
                if (bc+1 < N) sb.y = Bp[bc+1];
                if (bc+2 < N) sb.z = Bp[bc+2];
                if (bc+3 < N) sb.w = Bp[bc+3];
            }
        }
    };
    auto storeTile = [&]() {
        *(float2*)&As2[akq*4+0][2*ar]      = make_float2(sa0.x, sa0.x);
        *(float2*)&As2[akq*4+1][2*ar]      = make_float2(sa0.y, sa0.y);
        *(float2*)&As2[akq*4+2][2*ar]      = make_float2(sa0.z, sa0.z);
        *(float2*)&As2[akq*4+3][2*ar]      = make_float2(sa0.w, sa0.w);
        *(float2*)&As2[akq*4+0][2*(ar+64)] = make_float2(sa1.x, sa1.x);
        *(float2*)&As2[akq*4+1][2*(ar+64)] = make_float2(sa1.y, sa1.y);
        *(float2*)&As2[akq*4+2][2*(ar+64)] = make_float2(sa1.z, sa1.z);
        *(float2*)&As2[akq*4+3][2*(ar+64)] = make_float2(sa1.w, sa1.w);
        *(float4*)&Bs[br][bcq*4] = sb;
    };

    loadTile(kbeg);
    storeTile();
    __syncthreads();

    for (int k0 = kbeg; k0 < kend; k0 += 16) {
        const bool hasNext = (k0 + 16) < kend;
        if (hasNext) loadTile(k0 + 16);       // LDG overlapped with compute

        #pragma unroll
        for (int kk = 0; kk < 16; kk++) {
            ulonglong2 bq  = *(const ulonglong2*)&Bs[kk][tx*4];
            ulonglong2 a01 = *(const ulonglong2*)&As2[kk][ty*16];
            ulonglong2 a23 = *(const ulonglong2*)&As2[kk][ty*16+4];
            ulonglong2 a45 = *(const ulonglong2*)&As2[kk][ty*16+8];
            ulonglong2 a67 = *(const ulonglong2*)&As2[kk][ty*16+12];
            acc[0][0]=fma2(a01.x,bq.x,acc[0][0]); acc[0][1]=fma2(a01.x,bq.y,acc[0][1]);
            acc[1][0]=fma2(a01.y,bq.x,acc[1][0]); acc[1][1]=fma2(a01.y,bq.y,acc[1][1]);
            acc[2][0]=fma2(a23.x,bq.x,acc[2][0]); acc[2][1]=fma2(a23.x,bq.y,acc[2][1]);
            acc[3][0]=fma2(a23.y,bq.x,acc[3][0]); acc[3][1]=fma2(a23.y,bq.y,acc[3][1]);
            acc[4][0]=fma2(a45.x,bq.x,acc[4][0]); acc[4][1]=fma2(a45.x,bq.y,acc[4][1]);
            acc[5][0]=fma2(a45.y,bq.x,acc[5][0]); acc[5][1]=fma2(a45.y,bq.y,acc[5][1]);
            acc[6][0]=fma2(a67.x,bq.x,acc[6][0]); acc[6][1]=fma2(a67.x,bq.y,acc[6][1]);
            acc[7][0]=fma2(a67.y,bq.x,acc[7][0]); acc[7][1]=fma2(a67.y,bq.y,acc[7][1]);
        }
        if (hasNext) {
            __syncthreads();
            storeTile();
            __syncthreads();
        }
    }

    float* Co = Cpart + (size_t)z * M * N;
    #pragma unroll
    for (int r = 0; r < 8; r++) {
        const int gr = row0 + ty*8 + r;
        if (gr >= M) continue;
        float c[4];
        upk2(acc[r][0], c[0], c[1]);
        upk2(acc[r][1], c[2], c[3]);
        const int gc = col0 + tx*4;
        if (gc + 3 < N) {
            *(float4*)&Co[(size_t)gr * N + gc] = make_float4(c[0], c[1], c[2], c[3]);
        } else {
            #pragma unroll
            for (int j = 0; j < 4; j++)
                if (gc + j < N) Co[(size_t)gr * N + gc + j] = c[j];
        }
    }
}

// ---------------- reduce split-K partials (+optional bias) --------------
__global__ void reduce_k(float* __restrict__ out, const float* __restrict__ part,
                         int lenf4, int S, const float* __restrict__ bias, int N)
{
    int i = blockIdx.x * blockDim.x + threadIdx.x;
    if (i >= lenf4) return;
    const float4* p = (const float4*)part;
    float4 acc = p[i];
    if (S == 8) {
        float4 t[7];
        #pragma unroll
        for (int z = 0; z < 7; z++) t[z] = p[(size_t)(z+1) * lenf4 + i];
        #pragma unroll
        for (int z = 0; z < 7; z++) { acc.x += t[z].x; acc.y += t[z].y; acc.z += t[z].z; acc.w += t[z].w; }
    } else if (S == 4) {
        float4 t[3];
        #pragma unroll
        for (int z = 0; z < 3; z++) t[z] = p[(size_t)(z+1) * lenf4 + i];
        #pragma unroll
        for (int z = 0; z < 3; z++) { acc.x += t[z].x; acc.y += t[z].y; acc.z += t[z].z; acc.w += t[z].w; }
    } else if (S == 2) {
        float4 t = p[(size_t)lenf4 + i];
        acc.x += t.x; acc.y += t.y; acc.z += t.z; acc.w += t.w;
    }
    if (bias) {
        int col = (i * 4) % N;      // N % 4 == 0 for all uses
        acc.x += bias[col+0]; acc.y += bias[col+1];
        acc.z += bias[col+2]; acc.w += bias[col+3];
    }
    ((float4*)out)[i] = acc;
}

// ---------------- gn = normalize_rows(attributes @ att_g) ----------------
__global__ void gn_kernel(const float* __restrict__ attrs,
                          const float* __restrict__ att_g,
                          float* __restrict__ gn) {
    __shared__ float s_attr[8][DATT];
    __shared__ float s_red[8][4];
    const int c0 = blockIdx.x * 8;
    const int t = threadIdx.x;       // 128
    const int lane = t & 31, warp = t >> 5;

    for (int i = t; i < 8 * DATT; i += 128) {
        int r = i / DATT, k = i - r * DATT;
        s_attr[r][k] = attrs[(size_t)(c0 + r) * DATT + k];
    }
    __syncthreads();

    float acc[8] = {0.f,0.f,0.f,0.f,0.f,0.f,0.f,0.f};
    for (int k = 0; k < DATT; k++) {
        float w = att_g[(size_t)k * HH + t];
        #pragma unroll
        for (int r = 0; r < 8; r++) acc[r] = fmaf(s_attr[r][k], w, acc[r]);
    }
    #pragma unroll
    for (int r = 0; r < 8; r++) {
        float sq = acc[r] * acc[r];
        #pragma unroll
        for (int o = 16; o; o >>= 1) sq += __shfl_xor_sync(0xffffffffu, sq, o);
        if (lane == 0) s_red[r][warp] = sq;
    }
    __syncthreads();
    #pragma unroll
    for (int r = 0; r < 8; r++) {
        float tot = s_red[r][0] + s_red[r][1] + s_red[r][2] + s_red[r][3];
        float inv = 1.f / fmaxf(sqrtf(tot), 1e-12f);
        gn[(size_t)(c0 + r) * HH + t] = acc[r] * inv;
    }
}

// ---------------- sim = gn @ gn^T, masked+scaled in epilogue ------------
__global__ void sim_kernel(const float* __restrict__ gn, float* __restrict__ out)
{
    __shared__ __align__(16) float As2[16][140];
    __shared__ __align__(16) float Bs[16][68];
    const int tid = threadIdx.x;
    const int row0 = blockIdx.y * 64;
    const int col0 = blockIdx.x * 64;
    const int tx = tid & 15, ty = tid >> 4;
    const int ar = tid >> 2, akq = tid & 3;

    const float* Arp = gn + (size_t)min(row0 + ar, C_CLS - 1) * HH;
    const float* Brp = gn + (size_t)min(col0 + ar, C_CLS - 1) * HH;

    ull acc[4][2];
    #pragma unroll
    for (int r = 0; r < 4; r++) { acc[r][0] = 0ull; acc[r][1] = 0ull; }

    for (int k0 = 0; k0 < HH; k0 += 16) {
        float4 av = *(const float4*)(Arp + k0 + akq*4);
        float4 bv = *(const float4*)(Brp + k0 + akq*4);
        *(float2*)&As2[akq*4+0][2*ar] = make_float2(av.x, av.x);
        *(float2*)&As2[akq*4+1][2*ar] = make_float2(av.y, av.y);
        *(float2*)&As2[akq*4+2][2*ar] = make_float2(av.z, av.z);
        *(float2*)&As2[akq*4+3][2*ar] = make_float2(av.w, av.w);
        Bs[akq*4+0][ar] = bv.x; Bs[akq*4+1][ar] = bv.y;
        Bs[akq*4+2][ar] = bv.z; Bs[akq*4+3][ar] = bv.w;
        __syncthreads();
        #pragma unroll
        for (int kk = 0; kk < 16; kk++) {
            ulonglong2 bq  = *(const ulonglong2*)&Bs[kk][tx*4];
            ulonglong2 a01 = *(const ulonglong2*)&As2[kk][ty*8];
            ulonglong2 a23 = *(const ulonglong2*)&As2[kk][ty*8+4];
            acc[0][0]=fma2(a01.x,bq.x,acc[0][0]); acc[0][1]=fma2(a01.x,bq.y,acc[0][1]);
            acc[1][0]=fma2(a01.y,bq.x,acc[1][0]); acc[1][1]=fma2(a01.y,bq.y,acc[1][1]);
            acc[2][0]=fma2(a23.x,bq.x,acc[2][0]); acc[2][1]=fma2(a23.x,bq.y,acc[2][1]);
            acc[3][0]=fma2(a23.y,bq.x,acc[3][0]); acc[3][1]=fma2(a23.y,bq.y,acc[3][1]);
        }
        __syncthreads();
    }

    #pragma unroll
    for (int r = 0; r < 4; r++) {
        const int gr = row0 + ty*4 + r;
        if (gr >= C_CLS) continue;
        float c[4];
        upk2(acc[r][0], c[0], c[1]);
        upk2(acc[r][1], c[2], c[3]);
        #pragma unroll
        for (int j = 0; j < 4; j++) {
            const int gc = col0 + tx*4 + j;
            if (gc >= C_CLS) continue;
            float s = c[j];
            out[(size_t)gr * C_CLS + gc] = (s > THRESH) ? s * TEMP : -1e30f;
        }
    }
}

// ---------------- row softmax (in place, values pre-masked+scaled) ------
__global__ void softmax_kernel(float* __restrict__ attn)
{
    __shared__ float s_red[8];
    const int t = threadIdx.x, lane = t & 31, warp = t >> 5;
    float* row = attn + (size_t)blockIdx.x * C_CLS;

    float v[4];
    float m = -1e30f;
    #pragma unroll
    for (int i = 0; i < 4; i++) {
        int c = t + i * 256;
        v[i] = (c < C_CLS) ? row[c] : -1e30f;
        m = fmaxf(m, v[i]);
    }
    #pragma unroll
    for (int o = 16; o; o >>= 1) m = fmaxf(m, __shfl_xor_sync(0xffffffffu, m, o));
    if (lane == 0) s_red[warp] = m;
    __syncthreads();
    m = s_red[0];
    #pragma unroll
    for (int w = 1; w < 8; w++) m = fmaxf(m, s_red[w]);
    __syncthreads();

    float sum = 0.f;
    #pragma unroll
    for (int i = 0; i < 4; i++) {
        float e = (v[i] > -1e29f) ? __expf(v[i] - m) : 0.f;
        v[i] = e;
        sum += e;
    }
    #pragma unroll
    for (int o = 16; o; o >>= 1) sum += __shfl_xor_sync(0xffffffffu, sum, o);
    if (lane == 0) s_red[warp] = sum;
    __syncthreads();
    float tot = 0.f;
    #pragma unroll
    for (int w = 0; w < 8; w++) tot += s_red[w];
    float inv = 1.f / tot;
    #pragma unroll
    for (int i = 0; i < 4; i++) {
        int c = t + i * 256;
        if (c < C_CLS) row[c] = v[i] * inv;
    }
}

// ---------------- relation MLP: out[b,c] = fc_b + sum_h relu(a+p)*w -----
__global__ void relation_kernel(const float* __restrict__ img_h,
                                const float* __restrict__ proto_h,
                                const float* __restrict__ fc_w,
                                const float* __restrict__ fc_b,
                                float* __restrict__ out)
{
    __shared__ __align__(16) float s_a2[64][136];  // [h][2*b] duplicated
    __shared__ __align__(16) float s_p[64][68];    // [h][c]
    __shared__ __align__(16) float s_w2[2 * HH];   // duplicated weights
    const int tid = threadIdx.x;
    const int b0 = blockIdx.y * 64;
    const int c0 = blockIdx.x * 64;
    const int tx = tid & 15;        // c: tx*4
    const int ty = tid >> 4;        // b: ty*4
    const int bl = tid >> 2;        // loader row (0..63)
    const int hq = tid & 3;         // loader h-quad group

    if (tid < HH) { float w = fc_w[tid]; s_w2[2*tid] = w; s_w2[2*tid+1] = w; }

    ull acc[4][2];
    #pragma unroll
    for (int i = 0; i < 4; i++) { acc[i][0] = 0ull; acc[i][1] = 0ull; }

    const float* arow = img_h   + (size_t)(b0 + bl) * HH;
    const float* prow = proto_h + (size_t)min(c0 + bl, C_CLS - 1) * HH;

    for (int h0 = 0; h0 < HH; h0 += 64) {
        #pragma unroll
        for (int it = 0; it < 4; it++) {
            const int hh = (hq + 4*it) * 4;
            float4 va = *(const float4*)(arow + h0 + hh);
            float4 vp = *(const float4*)(prow + h0 + hh);
            *(float2*)&s_a2[hh+0][2*bl] = make_float2(va.x, va.x);
            *(float2*)&s_a2[hh+1][2*bl] = make_float2(va.y, va.y);
            *(float2*)&s_a2[hh+2][2*bl] = make_float2(va.z, va.z);
            *(float2*)&s_a2[hh+3][2*bl] = make_float2(va.w, va.w);
            s_p[hh+0][bl] = vp.x; s_p[hh+1][bl] = vp.y;
            s_p[hh+2][bl] = vp.z; s_p[hh+3][bl] = vp.w;
        }
        __syncthreads();
        #pragma unroll 4
        for (int hh = 0; hh < 64; hh++) {
            ull w2 = *(const ull*)&s_w2[2*(h0 + hh)];
            ulonglong2 aA = *(const ulonglong2*)&s_a2[hh][ty*8];
            ulonglong2 aB = *(const ulonglong2*)&s_a2[hh][ty*8+4];
            ulonglong2 pv = *(const ulonglong2*)&s_p[hh][tx*4];
            ull av[4] = {aA.x, aA.y, aB.x, aB.y};
            #pragma unroll
            for (int i = 0; i < 4; i++) {
                #pragma unroll
                for (int jp = 0; jp < 2; jp++) {
                    ull t = add2(av[i], jp ? pv.y : pv.x);
                    float t0, t1;
                    upk2(t, t0, t1);
                    t = pk2(fmaxf(t0, 0.f), fmaxf(t1, 0.f));
                    acc[i][jp] = fma2(t, w2, acc[i][jp]);
                }
            }
        }
        __syncthreads();
    }

    const float bias = fc_b[0];
    #pragma unroll
    for (int i = 0; i < 4; i++) {
        const int b = b0 + ty*4 + i;
        float c[4];
        upk2(acc[i][0], c[0], c[1]);
        upk2(acc[i][1], c[2], c[3]);
        const int cc = c0 + tx*4;
        if (cc + 3 < C_CLS) {
            float4 v = make_float4(c[0] + bias, c[1] + bias, c[2] + bias, c[3] + bias);
            *(float4*)&out[(size_t)b * C_CLS + cc] = v;
        } else {
            #pragma unroll
            for (int j = 0; j < 4; j++)
                if (cc + j < C_CLS) out[(size_t)b * C_CLS + cc + j] = c[j] + bias;
        }
    }
}

// ---------------- host launch ----------------
extern "C" void kernel_launch(void* const* d_in, const int* in_sizes, int n_in,
                              void* d_out, int out_size) {
    const float* image_feats = (const float*)d_in[0];  // [2048,2048]
    const float* img_proto   = (const float*)d_in[1];  // [1000,2048]
    const float* attributes  = (const float*)d_in[2];  // [1000,312]
    const float* att_g   = (const float*)d_in[4];      // [312,128]
    const float* slim_w  = (const float*)d_in[5];      // [2048,312]
    const float* slim_b  = (const float*)d_in[6];      // [312]
    const float* img_w   = (const float*)d_in[7];      // [2048,128]
    const float* proto_w = (const float*)d_in[8];      // [624,128]
    const float* proto_b = (const float*)d_in[9];      // [1,128]
    const float* fc_w    = (const float*)d_in[10];     // [128,1]
    const float* fc_b    = (const float*)d_in[11];     // [1]
    float* out = (float*)d_out;

    float *proto_red, *gnp, *attnp, *Mp, *proto_hp, *img_hp, *scrA, *scrB, *scrM;
    cudaGetSymbolAddress((void**)&proto_red, g_proto_red);
    cudaGetSymbolAddress((void**)&gnp,       g_gn);
    cudaGetSymbolAddress((void**)&attnp,     g_attn);
    cudaGetSymbolAddress((void**)&Mp,        g_M);
    cudaGetSymbolAddress((void**)&proto_hp,  g_proto_h);
    cudaGetSymbolAddress((void**)&img_hp,    g_img_h);
    cudaGetSymbolAddress((void**)&scrA,      g_scr_a);
    cudaGetSymbolAddress((void**)&scrB,      g_scr_b);
    cudaGetSymbolAddress((void**)&scrM,      g_scr_m);

    static cudaStream_t s1 = nullptr, s2 = nullptr, s3 = nullptr;
    static cudaEvent_t ev0 = nullptr, ev1 = nullptr, ev2 = nullptr, ev3 = nullptr;
    if (!s1) {
        cudaStreamCreateWithFlags(&s1, cudaStreamNonBlocking);
        cudaStreamCreateWithFlags(&s2, cudaStreamNonBlocking);
        cudaStreamCreateWithFlags(&s3, cudaStreamNonBlocking);
        cudaEventCreateWithFlags(&ev0, cudaEventDisableTiming);
        cudaEventCreateWithFlags(&ev1, cudaEventDisableTiming);
        cudaEventCreateWithFlags(&ev2, cudaEventDisableTiming);
        cudaEventCreateWithFlags(&ev3, cudaEventDisableTiming);
    }
    cudaStream_t s0 = 0;

    // fork
    cudaEventRecord(ev0, s0);
    cudaStreamWaitEvent(s1, ev0, 0);
    cudaStreamWaitEvent(s2, ev0, 0);
    cudaStreamWaitEvent(s3, ev0, 0);

    // ---- chain C (s1): gn -> sim -> softmax --------------------------------
    gn_kernel<<<C_CLS / 8, 128, 0, s1>>>(attributes, att_g, gnp);
    sim_kernel<<<dim3(16, 16), 256, 0, s1>>>(gnp, attnp);
    softmax_kernel<<<C_CLS, 256, 0, s1>>>(attnp);
    cudaEventRecord(ev1, s1);

    // ---- chain A (s2): img_h (split-K 8) -----------------------------------
    gemm128<<<dim3(2, 16, 8), 256, 0, s2>>>(image_feats, img_w, scrB,
                                            BB, HH, DIMG, 256);
    reduce_k<<<(BB*HH/4 + 255)/256, 256, 0, s2>>>(img_hp, scrB, BB*HH/4, 8, nullptr, HH);
    cudaEventRecord(ev2, s2);

    // ---- chain D (s3): M_top = attributes @ proto_w[0:312] (partials 0,1) --
    gemm128<<<dim3(2, 8, 2), 256, 0, s3>>>(attributes, proto_w, scrM,
                                           C_CLS, HH, DATT, 156);
    cudaEventRecord(ev3, s3);

    // ---- chain B (s0): proto_red -> M_bot -> M -> proto_h -> relation ------
    gemm128<<<dim3(5, 8, 8), 256, 0, s0>>>(img_proto, slim_w, scrA,
                                           C_CLS, DATT, DIMG, 256);
    reduce_k<<<(C_CLS*DATT/4 + 255)/256, 256, 0, s0>>>(proto_red, scrA, C_CLS*DATT/4, 8, slim_b, DATT);
    // M_bot partials into slices 2,3
    gemm128<<<dim3(2, 8, 2), 256, 0, s0>>>(proto_red, proto_w + (size_t)DATT * HH,
                                           scrM + 2 * (size_t)C_CLS * HH,
                                           C_CLS, HH, DATT, 156);
    // M = sum(4 slices) + proto_b
    cudaStreamWaitEvent(s0, ev3, 0);
    reduce_k<<<(C_CLS*HH/4 + 255)/256, 256, 0, s0>>>(Mp, scrM, C_CLS*HH/4, 4, proto_b, HH);

    // proto_h = attn @ M (split-K 8; proto_b folded via softmax row-sum = 1)
    cudaStreamWaitEvent(s0, ev1, 0);
    gemm128<<<dim3(2, 8, 8), 256, 0, s0>>>(attnp, Mp, scrA, C_CLS, HH, C_CLS, 128);
    reduce_k<<<(C_CLS*HH/4 + 255)/256, 256, 0, s0>>>(proto_hp, scrA, C_CLS*HH/4, 8, nullptr, HH);

    // ---- join: relation ----------------------------------------------------
    cudaStreamWaitEvent(s0, ev2, 0);
    relation_kernel<<<dim3(16, 32), 256, 0, s0>>>(img_hp, proto_hp, fc_w, fc_b, out);
}